// round 5
// baseline (speedup 1.0000x reference)
#include <cuda_runtime.h>
#include <cstdint>

// Problem constants
#define BATCH   128
#define SEQT    2048
#define EMB     128
#define HID     256
#define G4      1024
#define VOCABN  128
#define OUTN    2

// Decomposition: 16 clusters x 8 CTAs; cluster owns 8 batch elems split into
// two pipelined groups A (b0-3) and B (b4-7). CTA owns 32 hidden units.
// GEMM thread = (cp 0..63, kq 0..7) -> cols {2cp, 2cp+1}, k in [kq*32, kq*32+32).
#define CLUSTER   8
#define BG        8
#define BGH       4       // batch per group
#define USLICE    32
#define NCOL      128
#define NTHREADS  512
#define KQN       8
#define KSL       32
#define CHUNK_B   128     // bytes per cell-warp slice chunk
#define PHASE_TX  4096    // 8 senders * 4 warps * 128B arriving per phase

__device__ float d_table[VOCABN * G4];

__global__ void build_table_kernel(const float* __restrict__ emb,
                                   const float* __restrict__ W_ih,
                                   const float* __restrict__ b_ih,
                                   const float* __restrict__ b_hh) {
    __shared__ float se[EMB];
    int v = blockIdx.x;
    int tid = threadIdx.x;
    if (tid < EMB) se[tid] = emb[v * EMB + tid];
    __syncthreads();
    for (int j = tid; j < G4; j += blockDim.x) {
        float acc = b_ih[j] + b_hh[j];
        const float* w = W_ih + (size_t)j * EMB;
        #pragma unroll 8
        for (int e = 0; e < EMB; e++) acc += se[e] * w[e];
        d_table[v * G4 + j] = acc;
    }
}

// ---------- PTX helpers ----------
__device__ __forceinline__ uint32_t smem_u32(const void* p) {
    uint32_t a;
    asm("{ .reg .u64 t; cvta.to.shared.u64 t, %1; cvt.u32.u64 %0, t; }"
        : "=r"(a) : "l"(p));
    return a;
}
__device__ __forceinline__ void ffma2(unsigned long long& d, unsigned long long a,
                                      unsigned long long b, unsigned long long c) {
    asm("fma.rn.f32x2 %0, %1, %2, %3;" : "=l"(d) : "l"(a), "l"(b), "l"(c));
}
__device__ __forceinline__ unsigned long long dup2(float x) {
    unsigned long long r;
    uint32_t xi = __float_as_uint(x);
    asm("mov.b64 %0, {%1, %1};" : "=l"(r) : "r"(xi));
    return r;
}
__device__ __forceinline__ void unpack2(float& x, float& y, unsigned long long v) {
    uint32_t xi, yi;
    asm("mov.b64 {%0, %1}, %2;" : "=r"(xi), "=r"(yi) : "l"(v));
    x = __uint_as_float(xi); y = __uint_as_float(yi);
}
__device__ __forceinline__ void lds_v2_u64(unsigned long long& a, unsigned long long& b,
                                           uint32_t addr) {
    asm volatile("ld.shared.v2.b64 {%0, %1}, [%2];" : "=l"(a), "=l"(b) : "r"(addr));
}
__device__ __forceinline__ void cluster_sync_ptx() {
    asm volatile("barrier.cluster.arrive.aligned;" ::: "memory");
    asm volatile("barrier.cluster.wait.aligned;" ::: "memory");
}
__device__ __forceinline__ void mbar_init(uint32_t addr, uint32_t cnt) {
    asm volatile("mbarrier.init.shared.b64 [%0], %1;" :: "r"(addr), "r"(cnt) : "memory");
}
__device__ __forceinline__ void mbar_arm(uint32_t addr, uint32_t tx) {
    asm volatile("mbarrier.arrive.expect_tx.shared.b64 _, [%0], %1;"
                 :: "r"(addr), "r"(tx) : "memory");
}
__device__ __forceinline__ void mbar_wait(uint32_t addr, uint32_t parity) {
    uint32_t done;
    asm volatile(
        "{\n\t.reg .pred p;\n\t"
        "mbarrier.try_wait.parity.acquire.cta.shared::cta.b64 p, [%1], %2;\n\t"
        "selp.b32 %0, 1, 0, p;\n\t}"
        : "=r"(done) : "r"(addr), "r"(parity) : "memory");
    if (!done) {
        asm volatile(
            "{\n\t.reg .pred P1;\n\t"
            "WAIT_LOOP_%=:\n\t"
            "mbarrier.try_wait.parity.acquire.cta.shared::cta.b64 P1, [%0], %1, 0x989680;\n\t"
            "@P1 bra.uni WAIT_DONE_%=;\n\t"
            "bra.uni WAIT_LOOP_%=;\n\t"
            "WAIT_DONE_%=:\n\t}"
            :: "r"(addr), "r"(parity) : "memory");
    }
}
__device__ __forceinline__ void bulk_s2s_cluster(uint32_t dst_local_off, uint32_t src,
                                                 uint32_t bar_local_off, uint32_t rank,
                                                 uint32_t nbytes) {
    asm volatile(
        "{\n\t.reg .b32 rd, rb;\n\t"
        "mapa.shared::cluster.u32 rd, %0, %3;\n\t"
        "mapa.shared::cluster.u32 rb, %2, %3;\n\t"
        "cp.async.bulk.shared::cluster.shared::cta.mbarrier::complete_tx::bytes "
        "[rd], [%1], %4, [rb];\n\t}"
        :: "r"(dst_local_off), "r"(src), "r"(bar_local_off), "r"(rank), "r"(nbytes)
        : "memory");
}
__device__ __forceinline__ void fence_proxy_async_cta() {
    asm volatile("fence.proxy.async.shared::cta;" ::: "memory");
}
__device__ __forceinline__ uint32_t elect_one() {
    uint32_t pred;
    asm volatile(
        "{\n\t.reg .pred p;\n\t"
        "elect.sync _|p, 0xFFFFFFFF;\n\t"
        "selp.b32 %0, 1, 0, p;\n\t}" : "=r"(pred));
    return pred;
}
__device__ __forceinline__ float tanh_fast(float x) {
    float y;
    asm("tanh.approx.f32 %0, %1;" : "=f"(y) : "f"(x));
    return y;
}
__device__ __forceinline__ float sig_fast(float x) {
    return fmaf(0.5f, tanh_fast(0.5f * x), 0.5f);
}

// GEMM for one group-half: acc[col][b] += W[col][k]*h[k][b], b in 0..3.
__device__ __forceinline__ void gemm_half(uint32_t hb_p_addr, float* rp,
                                          const float* w0, const float* w1,
                                          int cp, int kq) {
    unsigned long long a00 = 0, a01 = 0, a10 = 0, a11 = 0;
    const uint32_t hbp = hb_p_addr + (uint32_t)kq * (KSL * BGH * 4);
    #pragma unroll
    for (int k = 0; k < KSL; k++) {
        unsigned long long h01, h23;
        lds_v2_u64(h01, h23, hbp + (uint32_t)k * 16u);
        unsigned long long ww0 = dup2(w0[k]);
        unsigned long long ww1 = dup2(w1[k]);
        ffma2(a00, ww0, h01, a00);
        ffma2(a01, ww0, h23, a01);
        ffma2(a10, ww1, h01, a10);
        ffma2(a11, ww1, h23, a11);
    }
    float c0b0, c0b1, c0b2, c0b3, c1b0, c1b1, c1b2, c1b3;
    unpack2(c0b0, c0b1, a00); unpack2(c0b2, c0b3, a01);
    unpack2(c1b0, c1b1, a10); unpack2(c1b2, c1b3, a11);
    float* r = rp + kq * (BGH * NCOL) + 2 * cp;
    *reinterpret_cast<float2*>(r + 0 * NCOL) = make_float2(c0b0, c1b0);
    *reinterpret_cast<float2*>(r + 1 * NCOL) = make_float2(c0b1, c1b1);
    *reinterpret_cast<float2*>(r + 2 * NCOL) = make_float2(c0b2, c1b2);
    *reinterpret_cast<float2*>(r + 3 * NCOL) = make_float2(c0b3, c1b3);
}

// Gating for one cell: returns hnew, updates c.
__device__ __forceinline__ float gate_cell(const float* rp, const float* xg,
                                           float& c, int bb, int uu) {
    float si = xg[0], sf = xg[1], sg = xg[2], so = xg[3];
    #pragma unroll
    for (int q = 0; q < KQN; q++) {
        float4 v = *reinterpret_cast<const float4*>(
            rp + q * (BGH * NCOL) + bb * NCOL + uu * 4);
        si += v.x; sf += v.y; sg += v.z; so += v.w;
    }
    float i_ = sig_fast(si);
    float f_ = sig_fast(sf);
    float g_ = tanh_fast(sg);
    float o_ = sig_fast(so);
    c = fmaf(f_, c, i_ * g_);
    return o_ * tanh_fast(c);
}

__global__ void __cluster_dims__(CLUSTER, 1, 1) __launch_bounds__(NTHREADS, 1)
lstm_persistent_kernel(const int* __restrict__ x,
                       const float* __restrict__ W_hh,
                       const float* __restrict__ fc_W,
                       const float* __restrict__ fc_b,
                       float* __restrict__ out) {
    __shared__ float hbA[2 * HID * BGH];              // [par][k][b] 8KB
    __shared__ float hbB[2 * HID * BGH];              // 8KB
    __shared__ float rpA[KQN * BGH * NCOL];           // 16KB
    __shared__ float rpB[KQN * BGH * NCOL];           // 16KB
    __shared__ __align__(16) float stA[2 * USLICE * BGH];  // [par][u][b] 1KB
    __shared__ __align__(16) float stB[2 * USLICE * BGH];  // 1KB
    __shared__ __align__(8) unsigned long long bars[4];    // A0 A1 B0 B1

    const int tid = threadIdx.x;
    uint32_t rank;
    asm("mov.u32 %0, %%cluster_ctarank;" : "=r"(rank));
    const int batch_base = (blockIdx.x / CLUSTER) * BG;

    // GEMM role
    const int cp = tid & 63;
    const int kq = tid >> 6;
    const int c0 = 2 * cp, c1 = 2 * cp + 1;
    const int grow0 = (c0 & 3) * HID + (int)rank * USLICE + (c0 >> 2);
    const int grow1 = (c1 & 3) * HID + (int)rank * USLICE + (c1 >> 2);

    float w0[KSL], w1[KSL];
    {
        const float4* wp0 = reinterpret_cast<const float4*>(
            W_hh + (size_t)grow0 * HID + kq * KSL);
        const float4* wp1 = reinterpret_cast<const float4*>(
            W_hh + (size_t)grow1 * HID + kq * KSL);
        #pragma unroll
        for (int i = 0; i < KSL / 4; i++) {
            float4 v0 = wp0[i], v1 = wp1[i];
            w0[4*i+0]=v0.x; w0[4*i+1]=v0.y; w0[4*i+2]=v0.z; w0[4*i+3]=v0.w;
            w1[4*i+0]=v1.x; w1[4*i+1]=v1.y; w1[4*i+2]=v1.z; w1[4*i+3]=v1.w;
        }
    }

    // Zero hidden buffers + init barriers
    for (int idx = tid; idx < 2 * HID * BGH; idx += NTHREADS) {
        hbA[idx] = 0.0f; hbB[idx] = 0.0f;
    }
    const uint32_t hbA_u32 = smem_u32(hbA);
    const uint32_t hbB_u32 = smem_u32(hbB);
    const uint32_t stA_u32 = smem_u32(stA);
    const uint32_t stB_u32 = smem_u32(stB);
    const uint32_t bars_u32 = smem_u32(bars);
    if (tid == 0) {
        #pragma unroll
        for (int i = 0; i < 4; i++) mbar_init(bars_u32 + 8u * i, 1);
    }
    __syncthreads();
    cluster_sync_ptx();            // zeros + bars visible cluster-wide
    if (tid == 0) {                // pre-arm all 4 barriers (first fills)
        #pragma unroll
        for (int i = 0; i < 4; i++) mbar_arm(bars_u32 + 8u * i, PHASE_TX);
    }

    // Cell role (tid < 128): warp w owns uu in [w*8, w*8+8), bb = lane&3.
    const int cw = tid >> 5;           // cell warp id 0..3 (valid for tid<128)
    const int lane = tid & 31;
    const int uu = cw * 8 + (lane >> 2);
    const int bb = lane & 3;
    float cA = 0.0f, cB = 0.0f;

    // xg state
    const int* xrowA = x + (size_t)(batch_base + bb) * SEQT;
    const int* xrowB = x + (size_t)(batch_base + 4 + bb) * SEQT;
    const float* tabu = d_table + (int)rank * USLICE + uu;  // + v*G4 + g*HID
    float xgA[4], xgB[4];
    if (tid < 128) {
        const float* ta = tabu + (size_t)xrowA[0] * G4;
        const float* tb = tabu + (size_t)xrowB[0] * G4;
        #pragma unroll
        for (int g = 0; g < 4; g++) { xgA[g] = ta[g * HID]; xgB[g] = tb[g * HID]; }
    }

    // Send destination offsets (constant parts)
    const uint32_t dst_row = rank * (USLICE * BGH * 4) + (uint32_t)cw * CHUNK_B;
    int phA0 = 0, phA1 = 0, phB0 = 0, phB1 = 0;

    #pragma unroll 1
    for (int t = 0; t < SEQT; t++) {
        const int p = t & 1;
        const int pn = p ^ 1;

        // ===== Phase P(t): gate_B(t-1) + send, then GEMM_A(t) =====
        if (tid < 128) {
            if (t > 0) {
                float h = gate_cell(rpB, xgB, cB, bb, uu);
                stB[p * 128 + tid] = h;              // chunk cw is 128B contiguous
                __syncwarp();
                if (elect_one()) {
                    fence_proxy_async_cta();
                    uint32_t src = stB_u32 + (uint32_t)p * 512u + (uint32_t)cw * CHUNK_B;
                    uint32_t dst = hbB_u32 + (uint32_t)p * (HID * BGH * 4) + dst_row;
                    uint32_t bar = bars_u32 + (uint32_t)(2 + p) * 8u;
                    #pragma unroll
                    for (uint32_t r2 = 0; r2 < CLUSTER; r2++)
                        bulk_s2s_cluster(dst, src, bar, r2, CHUNK_B);
                }
                // prefetch xgB(t) (used at P(t+1) / epilogue)
                const float* tb = tabu + (size_t)xrowB[t] * G4;
                #pragma unroll
                for (int g = 0; g < 4; g++) xgB[g] = tb[g * HID];
            }
        }
        if (t > 0) {
            if (p == 0) { mbar_wait(bars_u32 + 0, phA0); phA0 ^= 1; }
            else        { mbar_wait(bars_u32 + 8, phA1); phA1 ^= 1; }
            if (tid == 0) mbar_arm(bars_u32 + (uint32_t)p * 8u, PHASE_TX);
        }
        gemm_half(hbA_u32 + (uint32_t)p * (HID * BGH * 4), rpA, w0, w1, cp, kq);
        __syncthreads();

        // ===== Phase P'(t): gate_A(t) + send, then GEMM_B(t) =====
        if (tid < 128) {
            float h = gate_cell(rpA, xgA, cA, bb, uu);
            stA[pn * 128 + tid] = h;
            __syncwarp();
            if (elect_one()) {
                fence_proxy_async_cta();
                uint32_t src = stA_u32 + (uint32_t)pn * 512u + (uint32_t)cw * CHUNK_B;
                uint32_t dst = hbA_u32 + (uint32_t)pn * (HID * BGH * 4) + dst_row;
                uint32_t bar = bars_u32 + (uint32_t)pn * 8u;
                #pragma unroll
                for (uint32_t r2 = 0; r2 < CLUSTER; r2++)
                    bulk_s2s_cluster(dst, src, bar, r2, CHUNK_B);
            }
            if (t + 1 < SEQT) {   // prefetch xgA(t+1)
                const float* ta = tabu + (size_t)xrowA[t + 1] * G4;
                #pragma unroll
                for (int g = 0; g < 4; g++) xgA[g] = ta[g * HID];
            }
        }
        if (t > 0) {
            if (p == 0) { mbar_wait(bars_u32 + 16, phB0); phB0 ^= 1; }
            else        { mbar_wait(bars_u32 + 24, phB1); phB1 ^= 1; }
            if (tid == 0) mbar_arm(bars_u32 + (uint32_t)(2 + p) * 8u, PHASE_TX);
        }
        gemm_half(hbB_u32 + (uint32_t)p * (HID * BGH * 4), rpB, w0, w1, cp, kq);
        __syncthreads();
    }

    // ===== Epilogue: gate_B(2047) -> hB(2048) into hbB[0]; hA(2048) already
    // sent to hbA[0] during P'(2047). =====
    if (tid < 128) {
        float h = gate_cell(rpB, xgB, cB, bb, uu);
        stB[tid] = h;                       // parity 0
        __syncwarp();
        if (elect_one()) {
            fence_proxy_async_cta();
            uint32_t src = stB_u32 + (uint32_t)cw * CHUNK_B;
            uint32_t dst = hbB_u32 + dst_row;
            uint32_t bar = bars_u32 + 16u;  // barB[0]
            #pragma unroll
            for (uint32_t r2 = 0; r2 < CLUSTER; r2++)
                bulk_s2s_cluster(dst, src, bar, r2, CHUNK_B);
        }
    }
    // Final arrivals (also prevents exit while peers write our smem)
    mbar_wait(bars_u32 + 0,  phA0);   // hA(2048) in hbA[0]
    mbar_wait(bars_u32 + 16, phB0);   // hB(2048) in hbB[0]

    if (rank == 0 && tid < BG * OUTN) {
        int b = tid >> 1;
        int o = tid & 1;
        const float* hsrc = (b < BGH) ? hbA : hbB;
        int bl = (b < BGH) ? b : b - BGH;
        float acc = fc_b[o];
        #pragma unroll 8
        for (int k = 0; k < HID; k++)
            acc = fmaf(hsrc[k * BGH + bl], fc_W[o * HID + k], acc);
        out[(batch_base + b) * OUTN + o] = acc;
    }
}

extern "C" void kernel_launch(void* const* d_in, const int* in_sizes, int n_in,
                              void* d_out, int out_size) {
    (void)in_sizes; (void)n_in; (void)out_size;
    const int*   x     = (const int*)  d_in[0];
    const float* emb   = (const float*)d_in[1];
    const float* W_ih  = (const float*)d_in[2];
    const float* W_hh  = (const float*)d_in[3];
    const float* b_ih  = (const float*)d_in[4];
    const float* b_hh  = (const float*)d_in[5];
    const float* fc_W  = (const float*)d_in[6];
    const float* fc_b  = (const float*)d_in[7];
    float* out = (float*)d_out;

    build_table_kernel<<<VOCABN, 128>>>(emb, W_ih, b_ih, b_hh);
    lstm_persistent_kernel<<<BATCH / BG * CLUSTER, NTHREADS>>>(
        x, W_hh, fc_W, fc_b, out);
}